// round 10
// baseline (speedup 1.0000x reference)
#include <cuda_runtime.h>

#define NM       32
#define NIN      24
#define NSTEPS   199            // EVAL_PTS - 1
#define NB       2048           // fixed batch
#define WPB      8              // warps (rows) per block
#define THREADS  (WPB * 32)     // 256
#define GRID     (NB / WPB)     // 256, exact

static __device__ __forceinline__ float rg(const float* p, int i, int cap) {
    return (i < cap) ? p[i] : 0.0f;
}

// Complex fma: acc += a*b
static __device__ __forceinline__ void cfma(float2& acc, float2 a, float2 b) {
    acc.x = fmaf(a.x, b.x, fmaf(-a.y, b.y, acc.x));
    acc.y = fmaf(a.x, b.y, fmaf( a.y, b.x, acc.y));
}

// Per-thread row-slice of a 32x32 complex matmul: thread handles row r,
// cols c4..c4+3. TRANSA selects A[k][r] (plain transpose, no conjugation).
template <bool TRANSA>
static __device__ __forceinline__ void mmrow(float2 acc[4],
                                             const float2* __restrict__ A,
                                             const float2* __restrict__ B,
                                             int r, int c4) {
    acc[0] = acc[1] = acc[2] = acc[3] = make_float2(0.0f, 0.0f);
    #pragma unroll 8
    for (int k = 0; k < 32; k++) {
        float2 a = TRANSA ? A[k * 32 + r] : A[r * 32 + k];
        cfma(acc[0], a, B[k * 32 + c4 + 0]);
        cfma(acc[1], a, B[k * 32 + c4 + 1]);
        cfma(acc[2], a, B[k * 32 + c4 + 2]);
        cfma(acc[3], a, B[k * 32 + c4 + 3]);
    }
}

// =====================================================================
// Fused kernel. Phase 1 (matmul-only prelude, redundant per block):
//   X = i*H/256; U = (Taylor20(X))^(2^8); V = U^T U;
//   S = sum_{n=0}^{255} (V/1.1)^n via doubling; mix = (V S)/1.1;
//   T2 = -(kappa kappa^T) o (0.5 I + mix).
// Phase 2: RK4, one warp per batch row, lane per mode.
// Output modes (selected host-side from out_size):
//   mode 0: REAL-ONLY float32, layout (t, row, mode)        [out_size floats]
//   mode 1: interleaved re/im float pairs, same logical layout
// Every store index strictly < cap_f (floats).
// =====================================================================
__global__ void __launch_bounds__(THREADS, 1)
circuit_kernel(const float* __restrict__ A0r, const float* __restrict__ A0i,
               const float* __restrict__ omega, const float* __restrict__ kappa,
               const float* __restrict__ nl, const float* __restrict__ params,
               float* __restrict__ out,
               int a0r_cap, int a0i_cap, int om_cap, int ka_cap,
               int nl_cap, int par_cap, long long cap_f, int pair_mode)
{
    __shared__ float2 M0[1024], M1[1024], M2[1024], M3[1024];  // 32 KB
    __shared__ float2 shV[WPB][2][NM];                          // 4 KB

    const int tid = threadIdx.x;
    const int mr  = tid >> 3;         // matmul row, 0..31
    const int mc4 = (tid & 7) * 4;    // matmul col base, 0..28

    // ---------------- Phase 1: prelude ----------------

    // ---- build X = i*H / 256 into M0 ----
    {
        const float sc = 1.0f / 256.0f;
        #pragma unroll
        for (int j = 0; j < 4; j++) {
            int e = tid * 4 + j;
            int r = e >> 5, c = e & 31;
            float hr, hi;
            if (r < c) {
                int idx = r * 31 - (r * (r - 1)) / 2 + (c - r - 1);
                hr = rg(params, idx, par_cap);
                hi = rg(params, 496 + idx, par_cap);
            } else if (r > c) {
                int idx = c * 31 - (c * (c - 1)) / 2 + (r - c - 1);
                hr =  rg(params, idx, par_cap);
                hi = -rg(params, 496 + idx, par_cap);
            } else if (r < 31) {
                hr = rg(params, 992 + r, par_cap);
                hi = 0.0f;
            } else {
                float sd = 0.0f;
                for (int t = 0; t < 31; t++) sd += rg(params, 992 + t, par_cap);
                hr = -sd;
                hi = 0.0f;
            }
            M0[e] = make_float2(-hi * sc, hr * sc);   // i*H/256
        }
    }
    __syncthreads();

    // ---- E = I (M1) ----
    #pragma unroll
    for (int j = 0; j < 4; j++) {
        int e = tid * 4 + j;
        M1[e] = make_float2((e >> 5) == (e & 31) ? 1.0f : 0.0f, 0.0f);
    }
    __syncthreads();

    // ---- Horner: E = I + (X*E)/n, n = 20..1 ----
    float2* E = M1;
    float2* T = M2;
    for (int n = 20; n >= 1; n--) {
        float inv = 1.0f / (float)n;
        float2 acc[4];
        mmrow<false>(acc, M0, E, mr, mc4);
        #pragma unroll
        for (int j = 0; j < 4; j++) {
            float d = (mr == mc4 + j) ? 1.0f : 0.0f;
            T[mr * 32 + mc4 + j] = make_float2(d + acc[j].x * inv, acc[j].y * inv);
        }
        __syncthreads();
        float2* tmp = E; E = T; T = tmp;
    }

    // ---- 8 squarings ----
    for (int q = 0; q < 8; q++) {
        float2 acc[4];
        mmrow<false>(acc, E, E, mr, mc4);
        #pragma unroll
        for (int j = 0; j < 4; j++) T[mr * 32 + mc4 + j] = acc[j];
        __syncthreads();
        float2* tmp = E; E = T; T = tmp;
    }
    // E holds U.

    // ---- V = U^T U -> M0 ----
    {
        float2 acc[4];
        mmrow<true>(acc, E, E, mr, mc4);
        __syncthreads();
        #pragma unroll
        for (int j = 0; j < 4; j++) M0[mr * 32 + mc4 + j] = acc[j];
    }
    __syncthreads();

    // ---- Neumann via doubling: A = V/1.1; S = I+A; B = A ----
    float2* pS = E;
    float2* pB = T;
    float2* pT = M3;
    {
        const float ia = 1.0f / 1.1f;
        #pragma unroll
        for (int j = 0; j < 4; j++) {
            int e = tid * 4 + j;
            float2 v = M0[e];
            float2 a = make_float2(v.x * ia, v.y * ia);
            float d = ((e >> 5) == (e & 31)) ? 1.0f : 0.0f;
            pB[e] = a;
            pS[e] = make_float2(d + a.x, a.y);
        }
    }
    __syncthreads();

    for (int it = 0; it < 7; it++) {
        {
            float2 acc[4];
            mmrow<false>(acc, pB, pB, mr, mc4);
            #pragma unroll
            for (int j = 0; j < 4; j++) pT[mr * 32 + mc4 + j] = acc[j];
        }
        __syncthreads();
        { float2* t = pB; pB = pT; pT = t; }
        {
            float2 acc[4];
            mmrow<false>(acc, pS, pB, mr, mc4);
            #pragma unroll
            for (int j = 0; j < 4; j++) pT[mr * 32 + mc4 + j] = acc[j];
        }
        __syncthreads();
        #pragma unroll
        for (int j = 0; j < 4; j++) {
            int e = tid * 4 + j;
            float2 s = pS[e], t = pT[e];
            pS[e] = make_float2(s.x + t.x, s.y + t.y);
        }
        __syncthreads();
    }

    // ---- mix = (V*S)/1.1 -> pT ; T2 -> pB ----
    {
        float2 acc[4];
        mmrow<false>(acc, M0, pS, mr, mc4);
        #pragma unroll
        for (int j = 0; j < 4; j++) pT[mr * 32 + mc4 + j] = acc[j];
    }
    __syncthreads();
    {
        const float ia = 1.0f / 1.1f;
        #pragma unroll
        for (int j = 0; j < 4; j++) {
            int e = tid * 4 + j;
            int r = e >> 5, c = e & 31;
            float2 m = pT[e];
            float tr = fmaf(m.x, ia, (r == c) ? 0.5f : 0.0f);
            float ti = m.y * ia;
            float coef = -rg(kappa, r, ka_cap) * rg(kappa, c, ka_cap);
            pB[e] = make_float2(coef * tr, coef * ti);
        }
    }
    __syncthreads();
    const float2* __restrict__ T2 = pB;

    // ---------------- Phase 2: integrate ----------------
    const int warp = tid >> 5;
    const int lane = tid & 31;
    const int row  = blockIdx.x * WPB + warp;   // < 2048 always

    float2 b[NM];
    #pragma unroll
    for (int k = 0; k < NM; k++) b[k] = T2[lane * NM + k];

    const float wj  = rg(omega, lane, om_cap);
    const float nv  = rg(nl, 0, nl_cap);
    const float nl2 = nv * nv;

    float2 A;
    if (lane < NIN) {
        A.x = rg(A0r, row * NIN + lane, a0r_cap);
        A.y = rg(A0i, row * NIN + lane, a0i_cap);
    } else {
        A.x = 1.0f; A.y = 0.0f;
    }

    // Logical index of (t=0, row, mode):
    const long long stride_c = (long long)NB * NM;      // per time slice, complex elems
    long long cidx = (long long)row * NM + lane;

    if (pair_mode) {
        long long o = 2 * cidx;
        if (o + 1 < cap_f) { out[o] = A.x; out[o + 1] = A.y; }
    } else {
        if (cidx < cap_f) out[cidx] = A.x;              // real part only
    }

    const double dtd = 1.0 / (double)NSTEPS;
    const float dtf = (float)dtd;
    const float hdt = (float)(0.5 * dtd);
    const float dt6 = (float)(dtd / 6.0);

    float2* sh0 = &shV[warp][0][0];
    float2* sh1 = &shV[warp][1][0];

    for (int step = 0; step < NSTEPS; step++) {
        float2 k1, k2, k3, k4, st;
        sh0[lane] = A; __syncwarp();
        {
            float pr = 0.0f, pi = 0.0f;
            #pragma unroll
            for (int k = 0; k < NM; k++) {
                float2 t = b[k]; float2 v = sh0[k];
                pr = fmaf(t.x, v.x, pr); pr = fmaf(-t.y, v.y, pr);
                pi = fmaf(t.x, v.y, pi); pi = fmaf( t.y, v.x, pi);
            }
            float w = fmaf(nl2, fmaf(A.x, A.x, A.y * A.y), wj);
            k1 = make_float2(fmaf(-w, A.y, pr), fmaf(w, A.x, pi));
        }
        st = make_float2(fmaf(hdt, k1.x, A.x), fmaf(hdt, k1.y, A.y));
        sh1[lane] = st; __syncwarp();
        {
            float pr = 0.0f, pi = 0.0f;
            #pragma unroll
            for (int k = 0; k < NM; k++) {
                float2 t = b[k]; float2 v = sh1[k];
                pr = fmaf(t.x, v.x, pr); pr = fmaf(-t.y, v.y, pr);
                pi = fmaf(t.x, v.y, pi); pi = fmaf( t.y, v.x, pi);
            }
            float w = fmaf(nl2, fmaf(st.x, st.x, st.y * st.y), wj);
            k2 = make_float2(fmaf(-w, st.y, pr), fmaf(w, st.x, pi));
        }
        st = make_float2(fmaf(hdt, k2.x, A.x), fmaf(hdt, k2.y, A.y));
        sh0[lane] = st; __syncwarp();
        {
            float pr = 0.0f, pi = 0.0f;
            #pragma unroll
            for (int k = 0; k < NM; k++) {
                float2 t = b[k]; float2 v = sh0[k];
                pr = fmaf(t.x, v.x, pr); pr = fmaf(-t.y, v.y, pr);
                pi = fmaf(t.x, v.y, pi); pi = fmaf( t.y, v.x, pi);
            }
            float w = fmaf(nl2, fmaf(st.x, st.x, st.y * st.y), wj);
            k3 = make_float2(fmaf(-w, st.y, pr), fmaf(w, st.x, pi));
        }
        st = make_float2(fmaf(dtf, k3.x, A.x), fmaf(dtf, k3.y, A.y));
        sh1[lane] = st; __syncwarp();
        {
            float pr = 0.0f, pi = 0.0f;
            #pragma unroll
            for (int k = 0; k < NM; k++) {
                float2 t = b[k]; float2 v = sh1[k];
                pr = fmaf(t.x, v.x, pr); pr = fmaf(-t.y, v.y, pr);
                pi = fmaf(t.x, v.y, pi); pi = fmaf( t.y, v.x, pi);
            }
            float w = fmaf(nl2, fmaf(st.x, st.x, st.y * st.y), wj);
            k4 = make_float2(fmaf(-w, st.y, pr), fmaf(w, st.x, pi));
        }

        float sx = k1.x + 2.0f * (k2.x + k3.x) + k4.x;
        float sy = k1.y + 2.0f * (k2.y + k3.y) + k4.y;
        A.x = fmaf(dt6, sx, A.x);
        A.y = fmaf(dt6, sy, A.y);

        cidx += stride_c;
        if (pair_mode) {
            long long o = 2 * cidx;
            if (o + 1 < cap_f) { out[o] = A.x; out[o + 1] = A.y; }
        } else {
            if (cidx < cap_f) out[cidx] = A.x;
        }
    }
}

extern "C" void kernel_launch(void* const* d_in, const int* in_sizes, int n_in,
                              void* d_out, int out_size)
{
    // Positional binding per documented metadata order:
    //   A0_real, A0_imag, omega, kappa, nonlinearity, params
    const long long want[6] = {NB * NIN, NB * NIN, NM, NM, 1, NM * NM - 1};
    const float* P[6];
    int cap[6];
    for (int j = 0; j < 6; j++) {
        if (j < n_in) {
            P[j] = (const float*)d_in[j];
            long long s = in_sizes[j];
            cap[j] = (int)(s < want[j] ? s : want[j]);
        } else {
            P[j] = (const float*)d_out;   // never dereferenced (cap 0)
            cap[j] = 0;
        }
    }

    // Output interpretation. NEVER write more than out_size float elements.
    //   out_size >= 26,214,400  -> buffer holds re/im float pairs (pair_mode=1)
    //   otherwise               -> float32 real-part-only trajectory (mode 0)
    const long long PAIRS_F = 26214400LL;   // 2 * 200*2048*32
    long long cap_f = (long long)out_size;
    int pair_mode = (cap_f >= PAIRS_F) ? 1 : 0;
    if (cap_f > PAIRS_F) cap_f = PAIRS_F;

    circuit_kernel<<<GRID, THREADS>>>(P[0], P[1], P[2], P[3], P[4], P[5],
                                      (float*)d_out,
                                      cap[0], cap[1], cap[2], cap[3], cap[4], cap[5],
                                      cap_f, pair_mode);
}

// round 12
// speedup vs baseline: 1.0659x; 1.0659x over previous
#include <cuda_runtime.h>

#define NM       32
#define NIN      24
#define NSTEPS   199            // EVAL_PTS - 1
#define NB       2048           // fixed batch
#define WPB      7              // warps (rows) per block in integrator
#define ITHREADS (WPB * 32)     // 224
#define IGRID    ((NB + WPB - 1) / WPB)   // 293
#define PTHREADS 256            // prelude block

typedef unsigned long long u64;

__device__ float2 g_T2[NM * NM];   // T2 row-major [mode j][k]

static __device__ __forceinline__ float rg(const float* p, int i, int cap) {
    return (i < cap) ? p[i] : 0.0f;
}
static __device__ __forceinline__ u64 fma2(u64 a, u64 b, u64 c) {
    u64 d;
    asm("fma.rn.f32x2 %0, %1, %2, %3;" : "=l"(d) : "l"(a), "l"(b), "l"(c));
    return d;
}
static __device__ __forceinline__ u64 packf2(float x, float y) {
    u64 p;
    asm("mov.b64 %0, {%1, %2};" : "=l"(p) : "f"(x), "f"(y));
    return p;
}
static __device__ __forceinline__ float lo32(u64 v) { return __uint_as_float((unsigned)v); }
static __device__ __forceinline__ float hi32(u64 v) { return __uint_as_float((unsigned)(v >> 32)); }

// Per-thread row-slice of 32x32 complex matmul with packed f32x2 FMA.
// Thread computes row r, cols c4..c4+3 of A*B (or A^T*B).
// B is viewed as u64 {re,im} pairs. P[j]={Σar*br,Σar*bi}, Q[j]={Σai*br,Σai*bi}
// -> re = P.lo - Q.hi, im = P.hi + Q.lo.
template <bool TRANSA>
static __device__ __forceinline__ void mmrow2(float2 acc[4],
                                              const float2* __restrict__ A,
                                              const float2* __restrict__ B,
                                              int r, int c4) {
    const u64* __restrict__ Bq = (const u64*)B;
    u64 P0 = 0, P1 = 0, P2 = 0, P3 = 0, Q0 = 0, Q1 = 0, Q2 = 0, Q3 = 0;
    #pragma unroll 8
    for (int k = 0; k < 32; k++) {
        float2 a = TRANSA ? A[k * 32 + r] : A[r * 32 + k];
        u64 arr = packf2(a.x, a.x);
        u64 aii = packf2(a.y, a.y);
        u64 b0 = Bq[k * 32 + c4 + 0];
        u64 b1 = Bq[k * 32 + c4 + 1];
        u64 b2 = Bq[k * 32 + c4 + 2];
        u64 b3 = Bq[k * 32 + c4 + 3];
        P0 = fma2(arr, b0, P0); Q0 = fma2(aii, b0, Q0);
        P1 = fma2(arr, b1, P1); Q1 = fma2(aii, b1, Q1);
        P2 = fma2(arr, b2, P2); Q2 = fma2(aii, b2, Q2);
        P3 = fma2(arr, b3, P3); Q3 = fma2(aii, b3, Q3);
    }
    acc[0] = make_float2(lo32(P0) - hi32(Q0), hi32(P0) + lo32(Q0));
    acc[1] = make_float2(lo32(P1) - hi32(Q1), hi32(P1) + lo32(Q1));
    acc[2] = make_float2(lo32(P2) - hi32(Q2), hi32(P2) + lo32(Q2));
    acc[3] = make_float2(lo32(P3) - hi32(Q3), hi32(P3) + lo32(Q3));
}

// =====================================================================
// Prelude kernel (1 block, 256 threads): matmul-only, branch-free.
//   X = i*H/256; U = (Taylor20(X))^(2^8); V = U^T U;
//   S = sum_{n=0}^{255} (V/1.1)^n via doubling; mix = (V S)/1.1;
//   g_T2 = -(kappa kappa^T) o (0.5 I + mix).
// =====================================================================
__global__ void __launch_bounds__(PTHREADS, 1)
prelude_kernel(const float* __restrict__ kappa, const float* __restrict__ params,
               int ka_cap, int par_cap)
{
    __shared__ float2 M0[1024], M1[1024], M2[1024], M3[1024];  // 32 KB

    const int tid = threadIdx.x;
    const int mr  = tid >> 3;
    const int mc4 = (tid & 7) * 4;

    // ---- X = i*H/256 -> M0 ----
    {
        const float sc = 1.0f / 256.0f;
        #pragma unroll
        for (int j = 0; j < 4; j++) {
            int e = tid * 4 + j;
            int r = e >> 5, c = e & 31;
            float hr, hi;
            if (r < c) {
                int idx = r * 31 - (r * (r - 1)) / 2 + (c - r - 1);
                hr = rg(params, idx, par_cap);
                hi = rg(params, 496 + idx, par_cap);
            } else if (r > c) {
                int idx = c * 31 - (c * (c - 1)) / 2 + (r - c - 1);
                hr =  rg(params, idx, par_cap);
                hi = -rg(params, 496 + idx, par_cap);
            } else if (r < 31) {
                hr = rg(params, 992 + r, par_cap);
                hi = 0.0f;
            } else {
                float sd = 0.0f;
                for (int t = 0; t < 31; t++) sd += rg(params, 992 + t, par_cap);
                hr = -sd;
                hi = 0.0f;
            }
            M0[e] = make_float2(-hi * sc, hr * sc);
        }
    }

    // ---- E = I ----
    #pragma unroll
    for (int j = 0; j < 4; j++) {
        int e = tid * 4 + j;
        M1[e] = make_float2((e >> 5) == (e & 31) ? 1.0f : 0.0f, 0.0f);
    }
    __syncthreads();

    // ---- Horner: E = I + (X*E)/n, n = 20..1 ----
    float2* E = M1;
    float2* T = M2;
    for (int n = 20; n >= 1; n--) {
        float inv = 1.0f / (float)n;
        float2 acc[4];
        mmrow2<false>(acc, M0, E, mr, mc4);
        #pragma unroll
        for (int j = 0; j < 4; j++) {
            float d = (mr == mc4 + j) ? 1.0f : 0.0f;
            T[mr * 32 + mc4 + j] = make_float2(d + acc[j].x * inv, acc[j].y * inv);
        }
        __syncthreads();
        float2* tmp = E; E = T; T = tmp;
    }

    // ---- 8 squarings ----
    for (int q = 0; q < 8; q++) {
        float2 acc[4];
        mmrow2<false>(acc, E, E, mr, mc4);
        #pragma unroll
        for (int j = 0; j < 4; j++) T[mr * 32 + mc4 + j] = acc[j];
        __syncthreads();
        float2* tmp = E; E = T; T = tmp;
    }

    // ---- V = U^T U -> M0 ----
    {
        float2 acc[4];
        mmrow2<true>(acc, E, E, mr, mc4);
        __syncthreads();
        #pragma unroll
        for (int j = 0; j < 4; j++) M0[mr * 32 + mc4 + j] = acc[j];
    }
    __syncthreads();

    // ---- Neumann via doubling: A = V/1.1; S = I + A; B = A ----
    float2* pS = E;
    float2* pB = T;
    float2* pT = M3;
    {
        const float ia = 1.0f / 1.1f;
        #pragma unroll
        for (int j = 0; j < 4; j++) {
            int e = tid * 4 + j;
            float2 v = M0[e];
            float2 a = make_float2(v.x * ia, v.y * ia);
            float d = ((e >> 5) == (e & 31)) ? 1.0f : 0.0f;
            pB[e] = a;
            pS[e] = make_float2(d + a.x, a.y);
        }
    }
    __syncthreads();

    for (int it = 0; it < 7; it++) {
        {
            float2 acc[4];
            mmrow2<false>(acc, pB, pB, mr, mc4);
            #pragma unroll
            for (int j = 0; j < 4; j++) pT[mr * 32 + mc4 + j] = acc[j];
        }
        __syncthreads();
        { float2* t = pB; pB = pT; pT = t; }
        {
            float2 acc[4];
            mmrow2<false>(acc, pS, pB, mr, mc4);
            #pragma unroll
            for (int j = 0; j < 4; j++) pT[mr * 32 + mc4 + j] = acc[j];
        }
        __syncthreads();
        #pragma unroll
        for (int j = 0; j < 4; j++) {
            int e = tid * 4 + j;
            float2 s = pS[e], t = pT[e];
            pS[e] = make_float2(s.x + t.x, s.y + t.y);
        }
        __syncthreads();
    }

    // ---- mix = (V*S)/1.1 ; T2 = -(k k^T) o (0.5I + mix) -> g_T2 ----
    {
        float2 acc[4];
        mmrow2<false>(acc, M0, pS, mr, mc4);
        const float ia = 1.0f / 1.1f;
        #pragma unroll
        for (int j = 0; j < 4; j++) {
            int e = mr * 32 + mc4 + j;
            int r = mr, c = mc4 + j;
            float tr = fmaf(acc[j].x, ia, (r == c) ? 0.5f : 0.0f);
            float ti = acc[j].y * ia;
            float coef = -rg(kappa, r, ka_cap) * rg(kappa, c, ka_cap);
            g_T2[e] = make_float2(coef * tr, coef * ti);
        }
    }
}

// =====================================================================
// Integrator: one warp per batch row, lane j owns mode j.
// T2 row j in 32 u64 regs. Stage vector broadcast via shared float4
// {vr,vr,vi,vi}: per k = 1 LDS.128 + 2 FFMA2.
// =====================================================================
static __device__ __forceinline__ float2 f_eval(float2 V,
                                                const u64* __restrict__ bq,
                                                float4* __restrict__ shv,
                                                int lane, float wj, float nl2) {
    shv[lane] = make_float4(V.x, V.x, V.y, V.y);
    __syncwarp();
    u64 P0 = 0, P1 = 0, Q0 = 0, Q1 = 0;
    #pragma unroll
    for (int k = 0; k < NM; k += 2) {
        ulonglong2 u0 = *reinterpret_cast<const ulonglong2*>(shv + k);
        P0 = fma2(u0.x, bq[k], P0);       // {Σ vr·tr, Σ vr·ti}
        Q0 = fma2(u0.y, bq[k], Q0);       // {Σ vi·tr, Σ vi·ti}
        ulonglong2 u1 = *reinterpret_cast<const ulonglong2*>(shv + k + 1);
        P1 = fma2(u1.x, bq[k + 1], P1);
        Q1 = fma2(u1.y, bq[k + 1], Q1);
    }
    float pr = (lo32(P0) + lo32(P1)) - (hi32(Q0) + hi32(Q1));  // Σ(tr·vr − ti·vi)
    float pi = (hi32(P0) + hi32(P1)) + (lo32(Q0) + lo32(Q1));  // Σ(tr·vi + ti·vr)
    float w = fmaf(nl2, fmaf(V.x, V.x, V.y * V.y), wj);
    return make_float2(fmaf(-w, V.y, pr), fmaf(w, V.x, pi));
}

__global__ void __launch_bounds__(ITHREADS)
integrate_kernel(const float* __restrict__ A0r, const float* __restrict__ A0i,
                 const float* __restrict__ omega, const float* __restrict__ nl,
                 float* __restrict__ out,
                 int a0r_cap, int a0i_cap, int om_cap, int nl_cap,
                 long long cap_f, int pair_mode)
{
    __shared__ float4 shV[WPB][2][NM];   // 7 KB

    const int warp = threadIdx.x >> 5;
    const int lane = threadIdx.x & 31;
    const int row  = blockIdx.x * WPB + warp;
    if (row >= NB) return;

    // T2 row for this lane, packed {re,im} u64
    u64 bq[NM];
    const u64* t2q = (const u64*)g_T2;
    #pragma unroll
    for (int k = 0; k < NM; k++) bq[k] = t2q[lane * NM + k];

    const float wj  = rg(omega, lane, om_cap);
    const float nv  = rg(nl, 0, nl_cap);
    const float nl2 = nv * nv;

    float2 A;
    if (lane < NIN) {
        A.x = rg(A0r, row * NIN + lane, a0r_cap);
        A.y = rg(A0i, row * NIN + lane, a0i_cap);
    } else {
        A.x = 1.0f; A.y = 0.0f;
    }

    const long long stride_c = (long long)NB * NM;
    long long cidx = (long long)row * NM + lane;

    if (pair_mode) {
        long long o = 2 * cidx;
        if (o + 1 < cap_f) { out[o] = A.x; out[o + 1] = A.y; }
    } else {
        if (cidx < cap_f) out[cidx] = A.x;
    }

    const double dtd = 1.0 / (double)NSTEPS;
    const float dtf = (float)dtd;
    const float hdt = (float)(0.5 * dtd);
    const float dt6 = (float)(dtd / 6.0);

    float4* sh0 = &shV[warp][0][0];
    float4* sh1 = &shV[warp][1][0];

    for (int step = 0; step < NSTEPS; step++) {
        float2 k1 = f_eval(A, bq, sh0, lane, wj, nl2);
        float2 st = make_float2(fmaf(hdt, k1.x, A.x), fmaf(hdt, k1.y, A.y));
        float2 k2 = f_eval(st, bq, sh1, lane, wj, nl2);
        st = make_float2(fmaf(hdt, k2.x, A.x), fmaf(hdt, k2.y, A.y));
        float2 k3 = f_eval(st, bq, sh0, lane, wj, nl2);
        st = make_float2(fmaf(dtf, k3.x, A.x), fmaf(dtf, k3.y, A.y));
        float2 k4 = f_eval(st, bq, sh1, lane, wj, nl2);

        float sx = k1.x + 2.0f * (k2.x + k3.x) + k4.x;
        float sy = k1.y + 2.0f * (k2.y + k3.y) + k4.y;
        A.x = fmaf(dt6, sx, A.x);
        A.y = fmaf(dt6, sy, A.y);

        cidx += stride_c;
        if (pair_mode) {
            long long o = 2 * cidx;
            if (o + 1 < cap_f) { out[o] = A.x; out[o + 1] = A.y; }
        } else {
            if (cidx < cap_f) out[cidx] = A.x;
        }
    }
}

extern "C" void kernel_launch(void* const* d_in, const int* in_sizes, int n_in,
                              void* d_out, int out_size)
{
    // Positional binding per documented metadata order:
    //   A0_real, A0_imag, omega, kappa, nonlinearity, params
    const long long want[6] = {NB * NIN, NB * NIN, NM, NM, 1, NM * NM - 1};
    const float* P[6];
    int cap[6];
    for (int j = 0; j < 6; j++) {
        if (j < n_in) {
            P[j] = (const float*)d_in[j];
            long long s = in_sizes[j];
            cap[j] = (int)(s < want[j] ? s : want[j]);
        } else {
            P[j] = (const float*)d_out;   // never dereferenced (cap 0)
            cap[j] = 0;
        }
    }

    // Output interpretation — identical to the passing round 10 logic.
    const long long PAIRS_F = 26214400LL;   // 2 * 200*2048*32
    long long cap_f = (long long)out_size;
    int pair_mode = (cap_f >= PAIRS_F) ? 1 : 0;
    if (cap_f > PAIRS_F) cap_f = PAIRS_F;

    prelude_kernel<<<1, PTHREADS>>>(P[3], P[5], cap[3], cap[5]);
    integrate_kernel<<<IGRID, ITHREADS>>>(P[0], P[1], P[2], P[4],
                                          (float*)d_out,
                                          cap[0], cap[1], cap[2], cap[4],
                                          cap_f, pair_mode);
}

// round 13
// speedup vs baseline: 1.4532x; 1.3634x over previous
#include <cuda_runtime.h>

#define NM       32
#define NIN      24
#define NSTEPS   199            // EVAL_PTS - 1
#define NB       2048           // fixed batch
#define WPB      7              // warps (rows) per block in integrator
#define ITHREADS (WPB * 32)     // 224
#define IGRID    ((NB + WPB - 1) / WPB)   // 293
#define PTHREADS 512            // prelude block

typedef unsigned long long u64;

__device__ float2 g_T2[NM * NM];   // T2 row-major [mode j][k]

static __device__ __forceinline__ float rg(const float* p, int i, int cap) {
    return (i < cap) ? p[i] : 0.0f;
}
static __device__ __forceinline__ u64 fma2(u64 a, u64 b, u64 c) {
    u64 d;
    asm("fma.rn.f32x2 %0, %1, %2, %3;" : "=l"(d) : "l"(a), "l"(b), "l"(c));
    return d;
}
static __device__ __forceinline__ u64 packf2(float x, float y) {
    u64 p;
    asm("mov.b64 %0, {%1, %2};" : "=l"(p) : "f"(x), "f"(y));
    return p;
}
static __device__ __forceinline__ float lo32(u64 v) { return __uint_as_float((unsigned)v); }
static __device__ __forceinline__ float hi32(u64 v) { return __uint_as_float((unsigned)(v >> 32)); }

// ---------------------------------------------------------------------
// 32x32 complex matmul slice, 512-thread layout: thread owns row r,
// cols c2, c2+1. Swap trick: (ar+i·ai)(br+i·bi):
//   E += {ar,ai}*{br,bi} -> re = lo(E)-hi(E)
//   F += {ai,ar}*{br,bi} -> im = lo(F)+hi(F)
// ---------------------------------------------------------------------
template <bool TRANSA>
static __device__ __forceinline__ void mm2(float2 acc[2],
                                           const float2* __restrict__ A,
                                           const float2* __restrict__ B,
                                           int r, int c2) {
    const ulonglong2* __restrict__ B2 = (const ulonglong2*)B;
    u64 E0 = 0, F0 = 0, E1 = 0, F1 = 0;
    #pragma unroll 8
    for (int k = 0; k < 32; k++) {
        const float2 a = TRANSA ? A[k * 32 + r] : A[r * 32 + k];
        u64 au  = packf2(a.x, a.y);
        u64 asw = packf2(a.y, a.x);
        ulonglong2 bb = B2[k * 16 + (c2 >> 1)];
        E0 = fma2(au,  bb.x, E0);
        F0 = fma2(asw, bb.x, F0);
        E1 = fma2(au,  bb.y, E1);
        F1 = fma2(asw, bb.y, F1);
    }
    acc[0] = make_float2(lo32(E0) - hi32(E0), lo32(F0) + hi32(F0));
    acc[1] = make_float2(lo32(E1) - hi32(E1), lo32(F1) + hi32(F1));
}

// =====================================================================
// Prelude (1 block, 512 threads):
//   X = i*H; s = min scaling from min(inf-norm, 1.45*power-iter estimate);
//   U = (Taylor12(X/2^s))^(2^s); V = U^T U;
//   S = sum_{n=0}^{255} (V/1.1)^n via doubling; mix = (V S)/1.1;
//   g_T2 = -(kappa kappa^T) o (0.5 I + mix).
// =====================================================================
__global__ void __launch_bounds__(PTHREADS, 1)
prelude_kernel(const float* __restrict__ kappa, const float* __restrict__ params,
               int ka_cap, int par_cap)
{
    __shared__ __align__(16) float2 M0[1024], M1[1024], M2[1024], M3[1024];
    __shared__ int sh_s;

    const unsigned FULL = 0xffffffffu;
    const int tid = threadIdx.x;
    const int mr  = tid >> 4;          // row 0..31
    const int mc2 = (tid & 15) * 2;    // col base 0,2,..30

    // ---- X = i*H (unscaled) -> M0 ----
    #pragma unroll
    for (int j = 0; j < 2; j++) {
        int c = mc2 + j, r = mr;
        float hr, hi;
        if (r < c) {
            int idx = r * 31 - (r * (r - 1)) / 2 + (c - r - 1);
            hr = rg(params, idx, par_cap);
            hi = rg(params, 496 + idx, par_cap);
        } else if (r > c) {
            int idx = c * 31 - (c * (c - 1)) / 2 + (r - c - 1);
            hr =  rg(params, idx, par_cap);
            hi = -rg(params, 496 + idx, par_cap);
        } else if (r < 31) {
            hr = rg(params, 992 + r, par_cap);
            hi = 0.0f;
        } else {
            float sd = 0.0f;
            for (int t = 0; t < 31; t++) sd += rg(params, 992 + t, par_cap);
            hr = -sd;
            hi = 0.0f;
        }
        M0[r * 32 + c] = make_float2(-hi, hr);
    }
    __syncthreads();

    // ---- norm estimate on warp 0: inf-norm bound + power iteration ----
    if (tid < 32) {
        float v = 0.0f;
        for (int k = 0; k < 32; k++) {
            float2 a = M0[tid * 32 + k];
            v += fabsf(a.x) + fabsf(a.y);
        }
        float mx = v;
        #pragma unroll
        for (int o = 16; o; o >>= 1) mx = fmaxf(mx, __shfl_xor_sync(FULL, mx, o));

        float2 x = make_float2(1.0f, 0.07f * (float)tid - 1.0f);
        float est = 1.0f;
        for (int it = 0; it < 10; it++) {
            float yr = 0.0f, yi = 0.0f;
            #pragma unroll
            for (int k = 0; k < 32; k++) {
                float xr = __shfl_sync(FULL, x.x, k);
                float xi = __shfl_sync(FULL, x.y, k);
                float2 a = M0[tid * 32 + k];
                yr = fmaf(a.x, xr, fmaf(-a.y, xi, yr));
                yi = fmaf(a.x, xi, fmaf( a.y, xr, yi));
            }
            float nn = fmaf(yr, yr, yi * yi);
            #pragma unroll
            for (int o = 16; o; o >>= 1) nn += __shfl_xor_sync(FULL, nn, o);
            float nrm = sqrtf(fmaxf(nn, 1e-30f));
            est = nrm;
            float inv = 1.0f / nrm;
            x.x = yr * inv; x.y = yi * inv;
        }
        if (tid == 0) {
            float use = fminf(mx, 1.45f * est);
            int s = 0; float th = 0.45f;
            while (use > th && s < 15) { th *= 2.0f; s++; }
            sh_s = s;
        }
    }
    __syncthreads();
    const int s = sh_s;
    {
        float sc = ldexpf(1.0f, -s);
        #pragma unroll
        for (int j = 0; j < 2; j++) {
            int e = mr * 32 + mc2 + j;
            float2 xv = M0[e];
            M0[e] = make_float2(xv.x * sc, xv.y * sc);
        }
    }

    // ---- E = I -> M1 ----
    #pragma unroll
    for (int j = 0; j < 2; j++) {
        int e = mr * 32 + mc2 + j;
        M1[e] = make_float2((mr == mc2 + j) ? 1.0f : 0.0f, 0.0f);
    }
    __syncthreads();

    // ---- Horner: E = I + (X*E)/n, n = 12..1 ----
    float2* E = M1;
    float2* T = M2;
    for (int n = 12; n >= 1; n--) {
        float inv = 1.0f / (float)n;
        float2 acc[2];
        mm2<false>(acc, M0, E, mr, mc2);
        #pragma unroll
        for (int j = 0; j < 2; j++) {
            float d = (mr == mc2 + j) ? 1.0f : 0.0f;
            T[mr * 32 + mc2 + j] = make_float2(d + acc[j].x * inv, acc[j].y * inv);
        }
        __syncthreads();
        float2* tmp = E; E = T; T = tmp;
    }

    // ---- s squarings ----
    for (int q = 0; q < s; q++) {
        float2 acc[2];
        mm2<false>(acc, E, E, mr, mc2);
        #pragma unroll
        for (int j = 0; j < 2; j++) T[mr * 32 + mc2 + j] = acc[j];
        __syncthreads();
        float2* tmp = E; E = T; T = tmp;
    }

    // ---- V = U^T U -> M0 ----
    {
        float2 acc[2];
        mm2<true>(acc, E, E, mr, mc2);
        __syncthreads();
        #pragma unroll
        for (int j = 0; j < 2; j++) M0[mr * 32 + mc2 + j] = acc[j];
    }
    __syncthreads();

    // ---- Neumann via doubling: A = V/1.1; S = I + A; B = A ----
    float2* pS = E;
    float2* pB = T;
    float2* pT = M3;
    {
        const float ia = 1.0f / 1.1f;
        #pragma unroll
        for (int j = 0; j < 2; j++) {
            int e = mr * 32 + mc2 + j;
            float2 v = M0[e];
            float2 a = make_float2(v.x * ia, v.y * ia);
            float d = (mr == mc2 + j) ? 1.0f : 0.0f;
            pB[e] = a;
            pS[e] = make_float2(d + a.x, a.y);
        }
    }
    __syncthreads();

    for (int it = 0; it < 7; it++) {
        {
            float2 acc[2];
            mm2<false>(acc, pB, pB, mr, mc2);
            #pragma unroll
            for (int j = 0; j < 2; j++) pT[mr * 32 + mc2 + j] = acc[j];
        }
        __syncthreads();
        { float2* t = pB; pB = pT; pT = t; }
        {
            float2 acc[2];
            mm2<false>(acc, pS, pB, mr, mc2);
            #pragma unroll
            for (int j = 0; j < 2; j++) pT[mr * 32 + mc2 + j] = acc[j];
        }
        __syncthreads();
        #pragma unroll
        for (int j = 0; j < 2; j++) {
            int e = mr * 32 + mc2 + j;
            float2 sv = pS[e], tv = pT[e];
            pS[e] = make_float2(sv.x + tv.x, sv.y + tv.y);
        }
        __syncthreads();
    }

    // ---- mix = (V*S)/1.1 ; g_T2 = -(k k^T) o (0.5I + mix) ----
    {
        float2 acc[2];
        mm2<false>(acc, M0, pS, mr, mc2);
        const float ia = 1.0f / 1.1f;
        #pragma unroll
        for (int j = 0; j < 2; j++) {
            int r = mr, c = mc2 + j;
            float tr = fmaf(acc[j].x, ia, (r == c) ? 0.5f : 0.0f);
            float ti = acc[j].y * ia;
            float coef = -rg(kappa, r, ka_cap) * rg(kappa, c, ka_cap);
            g_T2[r * 32 + c] = make_float2(coef * tr, coef * ti);
        }
    }
}

// =====================================================================
// Integrator: one warp per batch row, lane j owns mode j.
// Stage vector in shared as plain {vr,vi} (LDS.64 broadcast = 1 phase).
// T2 row split: k=0..15 pre-duplicated in regs ({tr,tr},{ti,ti}; 0 movs);
// k=16..31 packed {tr,ti} with the V-swap trick (2 movs per k).
// Per k: 1 LDS.64 + 2 fma2 (+0-2 movs). L1 phases halved vs R12.
// =====================================================================
#define DUPK 16

static __device__ __forceinline__ float2 f_eval(float2 V,
                                                const u64* __restrict__ crr,
                                                const u64* __restrict__ cii,
                                                const u64* __restrict__ bq,
                                                float2* __restrict__ shv,
                                                int lane, float wj, float nl2) {
    shv[lane] = V;
    __syncwarp();
    const u64* __restrict__ shq = (const u64*)shv;
    u64 Aa = 0, Ab = 0, Ae = 0, Af = 0;
    #pragma unroll
    for (int k = 0; k < DUPK; k++) {
        u64 W = shq[k];                       // {vr, vi}
        Aa = fma2(W, crr[k], Aa);             // {Σvr·tr, Σvi·tr}
        Ab = fma2(W, cii[k], Ab);             // {Σvr·ti, Σvi·ti}
    }
    #pragma unroll
    for (int k = 0; k < NM - DUPK; k++) {
        u64 W = shq[DUPK + k];                // {vr, vi}
        u64 Wsw = packf2(hi32(W), lo32(W));   // {vi, vr}
        Ae = fma2(W,   bq[k], Ae);            // {Σvr·tr, Σvi·ti}
        Af = fma2(Wsw, bq[k], Af);            // {Σvi·tr, Σvr·ti}
    }
    float pr = (lo32(Aa) - hi32(Ab)) + (lo32(Ae) - hi32(Ae));
    float pi = (hi32(Aa) + lo32(Ab)) + (lo32(Af) + hi32(Af));
    float w = fmaf(nl2, fmaf(V.x, V.x, V.y * V.y), wj);
    return make_float2(fmaf(-w, V.y, pr), fmaf(w, V.x, pi));
}

__global__ void __launch_bounds__(ITHREADS, 2)
integrate_kernel(const float* __restrict__ A0r, const float* __restrict__ A0i,
                 const float* __restrict__ omega, const float* __restrict__ nl,
                 float* __restrict__ out,
                 int a0r_cap, int a0i_cap, int om_cap, int nl_cap,
                 long long cap_f, int pair_mode)
{
    __shared__ float2 shV[WPB][2][NM];   // 3.5 KB

    const int warp = threadIdx.x >> 5;
    const int lane = threadIdx.x & 31;
    const int row  = blockIdx.x * WPB + warp;
    if (row >= NB) return;

    // T2 row for this lane
    u64 crr[DUPK], cii[DUPK], bq[NM - DUPK];
    #pragma unroll
    for (int k = 0; k < DUPK; k++) {
        float2 t = g_T2[lane * NM + k];
        crr[k] = packf2(t.x, t.x);
        cii[k] = packf2(t.y, t.y);
    }
    {
        const u64* t2q = (const u64*)g_T2;
        #pragma unroll
        for (int k = 0; k < NM - DUPK; k++) bq[k] = t2q[lane * NM + DUPK + k];
    }

    const float wj  = rg(omega, lane, om_cap);
    const float nv  = rg(nl, 0, nl_cap);
    const float nl2 = nv * nv;

    float2 A;
    if (lane < NIN) {
        A.x = rg(A0r, row * NIN + lane, a0r_cap);
        A.y = rg(A0i, row * NIN + lane, a0i_cap);
    } else {
        A.x = 1.0f; A.y = 0.0f;
    }

    const long long stride_c = (long long)NB * NM;
    long long cidx = (long long)row * NM + lane;

    if (pair_mode) {
        long long o = 2 * cidx;
        if (o + 1 < cap_f) { out[o] = A.x; out[o + 1] = A.y; }
    } else {
        if (cidx < cap_f) out[cidx] = A.x;
    }

    const double dtd = 1.0 / (double)NSTEPS;
    const float dtf = (float)dtd;
    const float hdt = (float)(0.5 * dtd);
    const float dt6 = (float)(dtd / 6.0);

    float2* sh0 = &shV[warp][0][0];
    float2* sh1 = &shV[warp][1][0];

    for (int step = 0; step < NSTEPS; step++) {
        float2 k1 = f_eval(A, crr, cii, bq, sh0, lane, wj, nl2);
        float2 st = make_float2(fmaf(hdt, k1.x, A.x), fmaf(hdt, k1.y, A.y));
        float2 k2 = f_eval(st, crr, cii, bq, sh1, lane, wj, nl2);
        st = make_float2(fmaf(hdt, k2.x, A.x), fmaf(hdt, k2.y, A.y));
        float2 k3 = f_eval(st, crr, cii, bq, sh0, lane, wj, nl2);
        st = make_float2(fmaf(dtf, k3.x, A.x), fmaf(dtf, k3.y, A.y));
        float2 k4 = f_eval(st, crr, cii, bq, sh1, lane, wj, nl2);

        float sx = k1.x + 2.0f * (k2.x + k3.x) + k4.x;
        float sy = k1.y + 2.0f * (k2.y + k3.y) + k4.y;
        A.x = fmaf(dt6, sx, A.x);
        A.y = fmaf(dt6, sy, A.y);

        cidx += stride_c;
        if (pair_mode) {
            long long o = 2 * cidx;
            if (o + 1 < cap_f) { out[o] = A.x; out[o + 1] = A.y; }
        } else {
            if (cidx < cap_f) out[cidx] = A.x;
        }
    }
}

extern "C" void kernel_launch(void* const* d_in, const int* in_sizes, int n_in,
                              void* d_out, int out_size)
{
    // Positional binding per documented metadata order:
    //   A0_real, A0_imag, omega, kappa, nonlinearity, params
    const long long want[6] = {NB * NIN, NB * NIN, NM, NM, 1, NM * NM - 1};
    const float* P[6];
    int cap[6];
    for (int j = 0; j < 6; j++) {
        if (j < n_in) {
            P[j] = (const float*)d_in[j];
            long long s = in_sizes[j];
            cap[j] = (int)(s < want[j] ? s : want[j]);
        } else {
            P[j] = (const float*)d_out;   // never dereferenced (cap 0)
            cap[j] = 0;
        }
    }

    // Output interpretation — identical to the passing round 10/12 logic.
    const long long PAIRS_F = 26214400LL;   // 2 * 200*2048*32
    long long cap_f = (long long)out_size;
    int pair_mode = (cap_f >= PAIRS_F) ? 1 : 0;
    if (cap_f > PAIRS_F) cap_f = PAIRS_F;

    prelude_kernel<<<1, PTHREADS>>>(P[3], P[5], cap[3], cap[5]);
    integrate_kernel<<<IGRID, ITHREADS>>>(P[0], P[1], P[2], P[4],
                                          (float*)d_out,
                                          cap[0], cap[1], cap[2], cap[4],
                                          cap_f, pair_mode);
}

// round 14
// speedup vs baseline: 1.5796x; 1.0870x over previous
#include <cuda_runtime.h>

#define NM       32
#define NIN      24
#define NSTEPS   199            // EVAL_PTS - 1
#define NB       2048           // fixed batch
#define WPB      7              // warps per block; each warp integrates 2 rows
#define RPB      (2 * WPB)      // 14 rows per block
#define ITHREADS (WPB * 32)     // 224
#define IGRID    ((NB + RPB - 1) / RPB)   // 147  (one block per SM, one wave)
#define PTHREADS 512            // prelude block

typedef unsigned long long u64;

__device__ float2 g_T2[NM * NM];   // T2 row-major [mode j][k]

static __device__ __forceinline__ float rg(const float* p, int i, int cap) {
    return (i < cap) ? p[i] : 0.0f;
}
static __device__ __forceinline__ u64 fma2(u64 a, u64 b, u64 c) {
    u64 d;
    asm("fma.rn.f32x2 %0, %1, %2, %3;" : "=l"(d) : "l"(a), "l"(b), "l"(c));
    return d;
}
static __device__ __forceinline__ u64 packf2(float x, float y) {
    u64 p;
    asm("mov.b64 %0, {%1, %2};" : "=l"(p) : "f"(x), "f"(y));
    return p;
}
static __device__ __forceinline__ float lo32(u64 v) { return __uint_as_float((unsigned)v); }
static __device__ __forceinline__ float hi32(u64 v) { return __uint_as_float((unsigned)(v >> 32)); }

// ---------------------------------------------------------------------
// 32x32 complex matmul slice for the prelude (512-thread layout):
// thread owns row r, cols c2, c2+1. Swap trick:
//   E += {ar,ai}*{br,bi} -> re = lo(E)-hi(E)
//   F += {ai,ar}*{br,bi} -> im = lo(F)+hi(F)
// ---------------------------------------------------------------------
template <bool TRANSA>
static __device__ __forceinline__ void mm2(float2 acc[2],
                                           const float2* __restrict__ A,
                                           const float2* __restrict__ B,
                                           int r, int c2) {
    const ulonglong2* __restrict__ B2 = (const ulonglong2*)B;
    u64 E0 = 0, F0 = 0, E1 = 0, F1 = 0;
    #pragma unroll 8
    for (int k = 0; k < 32; k++) {
        const float2 a = TRANSA ? A[k * 32 + r] : A[r * 32 + k];
        u64 au  = packf2(a.x, a.y);
        u64 asw = packf2(a.y, a.x);
        ulonglong2 bb = B2[k * 16 + (c2 >> 1)];
        E0 = fma2(au,  bb.x, E0);
        F0 = fma2(asw, bb.x, F0);
        E1 = fma2(au,  bb.y, E1);
        F1 = fma2(asw, bb.y, F1);
    }
    acc[0] = make_float2(lo32(E0) - hi32(E0), lo32(F0) + hi32(F0));
    acc[1] = make_float2(lo32(E1) - hi32(E1), lo32(F1) + hi32(F1));
}

// =====================================================================
// Prelude (1 block, 512 threads) — unchanged from the passing R13:
//   X = i*H; s from min(inf-norm, 1.45*power-iter estimate);
//   U = (Taylor12(X/2^s))^(2^s); V = U^T U;
//   S = sum_{n=0}^{255} (V/1.1)^n via doubling; mix = (V S)/1.1;
//   g_T2 = -(kappa kappa^T) o (0.5 I + mix).
// =====================================================================
__global__ void __launch_bounds__(PTHREADS, 1)
prelude_kernel(const float* __restrict__ kappa, const float* __restrict__ params,
               int ka_cap, int par_cap)
{
    __shared__ __align__(16) float2 M0[1024], M1[1024], M2[1024], M3[1024];
    __shared__ int sh_s;

    const unsigned FULL = 0xffffffffu;
    const int tid = threadIdx.x;
    const int mr  = tid >> 4;          // row 0..31
    const int mc2 = (tid & 15) * 2;    // col base 0,2,..30

    // ---- X = i*H (unscaled) -> M0 ----
    #pragma unroll
    for (int j = 0; j < 2; j++) {
        int c = mc2 + j, r = mr;
        float hr, hi;
        if (r < c) {
            int idx = r * 31 - (r * (r - 1)) / 2 + (c - r - 1);
            hr = rg(params, idx, par_cap);
            hi = rg(params, 496 + idx, par_cap);
        } else if (r > c) {
            int idx = c * 31 - (c * (c - 1)) / 2 + (r - c - 1);
            hr =  rg(params, idx, par_cap);
            hi = -rg(params, 496 + idx, par_cap);
        } else if (r < 31) {
            hr = rg(params, 992 + r, par_cap);
            hi = 0.0f;
        } else {
            float sd = 0.0f;
            for (int t = 0; t < 31; t++) sd += rg(params, 992 + t, par_cap);
            hr = -sd;
            hi = 0.0f;
        }
        M0[r * 32 + c] = make_float2(-hi, hr);
    }
    __syncthreads();

    // ---- norm estimate on warp 0 ----
    if (tid < 32) {
        float v = 0.0f;
        for (int k = 0; k < 32; k++) {
            float2 a = M0[tid * 32 + k];
            v += fabsf(a.x) + fabsf(a.y);
        }
        float mx = v;
        #pragma unroll
        for (int o = 16; o; o >>= 1) mx = fmaxf(mx, __shfl_xor_sync(FULL, mx, o));

        float2 x = make_float2(1.0f, 0.07f * (float)tid - 1.0f);
        float est = 1.0f;
        for (int it = 0; it < 10; it++) {
            float yr = 0.0f, yi = 0.0f;
            #pragma unroll
            for (int k = 0; k < 32; k++) {
                float xr = __shfl_sync(FULL, x.x, k);
                float xi = __shfl_sync(FULL, x.y, k);
                float2 a = M0[tid * 32 + k];
                yr = fmaf(a.x, xr, fmaf(-a.y, xi, yr));
                yi = fmaf(a.x, xi, fmaf( a.y, xr, yi));
            }
            float nn = fmaf(yr, yr, yi * yi);
            #pragma unroll
            for (int o = 16; o; o >>= 1) nn += __shfl_xor_sync(FULL, nn, o);
            float nrm = sqrtf(fmaxf(nn, 1e-30f));
            est = nrm;
            float inv = 1.0f / nrm;
            x.x = yr * inv; x.y = yi * inv;
        }
        if (tid == 0) {
            float use = fminf(mx, 1.45f * est);
            int s = 0; float th = 0.45f;
            while (use > th && s < 15) { th *= 2.0f; s++; }
            sh_s = s;
        }
    }
    __syncthreads();
    const int s = sh_s;
    {
        float sc = ldexpf(1.0f, -s);
        #pragma unroll
        for (int j = 0; j < 2; j++) {
            int e = mr * 32 + mc2 + j;
            float2 xv = M0[e];
            M0[e] = make_float2(xv.x * sc, xv.y * sc);
        }
    }

    // ---- E = I ----
    #pragma unroll
    for (int j = 0; j < 2; j++) {
        int e = mr * 32 + mc2 + j;
        M1[e] = make_float2((mr == mc2 + j) ? 1.0f : 0.0f, 0.0f);
    }
    __syncthreads();

    // ---- Horner: E = I + (X*E)/n, n = 12..1 ----
    float2* E = M1;
    float2* T = M2;
    for (int n = 12; n >= 1; n--) {
        float inv = 1.0f / (float)n;
        float2 acc[2];
        mm2<false>(acc, M0, E, mr, mc2);
        #pragma unroll
        for (int j = 0; j < 2; j++) {
            float d = (mr == mc2 + j) ? 1.0f : 0.0f;
            T[mr * 32 + mc2 + j] = make_float2(d + acc[j].x * inv, acc[j].y * inv);
        }
        __syncthreads();
        float2* tmp = E; E = T; T = tmp;
    }

    // ---- s squarings ----
    for (int q = 0; q < s; q++) {
        float2 acc[2];
        mm2<false>(acc, E, E, mr, mc2);
        #pragma unroll
        for (int j = 0; j < 2; j++) T[mr * 32 + mc2 + j] = acc[j];
        __syncthreads();
        float2* tmp = E; E = T; T = tmp;
    }

    // ---- V = U^T U -> M0 ----
    {
        float2 acc[2];
        mm2<true>(acc, E, E, mr, mc2);
        __syncthreads();
        #pragma unroll
        for (int j = 0; j < 2; j++) M0[mr * 32 + mc2 + j] = acc[j];
    }
    __syncthreads();

    // ---- Neumann via doubling: A = V/1.1; S = I + A; B = A ----
    float2* pS = E;
    float2* pB = T;
    float2* pT = M3;
    {
        const float ia = 1.0f / 1.1f;
        #pragma unroll
        for (int j = 0; j < 2; j++) {
            int e = mr * 32 + mc2 + j;
            float2 v = M0[e];
            float2 a = make_float2(v.x * ia, v.y * ia);
            float d = (mr == mc2 + j) ? 1.0f : 0.0f;
            pB[e] = a;
            pS[e] = make_float2(d + a.x, a.y);
        }
    }
    __syncthreads();

    for (int it = 0; it < 7; it++) {
        {
            float2 acc[2];
            mm2<false>(acc, pB, pB, mr, mc2);
            #pragma unroll
            for (int j = 0; j < 2; j++) pT[mr * 32 + mc2 + j] = acc[j];
        }
        __syncthreads();
        { float2* t = pB; pB = pT; pT = t; }
        {
            float2 acc[2];
            mm2<false>(acc, pS, pB, mr, mc2);
            #pragma unroll
            for (int j = 0; j < 2; j++) pT[mr * 32 + mc2 + j] = acc[j];
        }
        __syncthreads();
        #pragma unroll
        for (int j = 0; j < 2; j++) {
            int e = mr * 32 + mc2 + j;
            float2 sv = pS[e], tv = pT[e];
            pS[e] = make_float2(sv.x + tv.x, sv.y + tv.y);
        }
        __syncthreads();
    }

    // ---- mix = (V*S)/1.1 ; g_T2 = -(k k^T) o (0.5I + mix) ----
    {
        float2 acc[2];
        mm2<false>(acc, M0, pS, mr, mc2);
        const float ia = 1.0f / 1.1f;
        #pragma unroll
        for (int j = 0; j < 2; j++) {
            int r = mr, c = mc2 + j;
            float tr = fmaf(acc[j].x, ia, (r == c) ? 0.5f : 0.0f);
            float ti = acc[j].y * ia;
            float coef = -rg(kappa, r, ka_cap) * rg(kappa, c, ka_cap);
            g_T2[r * 32 + c] = make_float2(coef * tr, coef * ti);
        }
    }
}

// =====================================================================
// Integrator: each warp integrates TWO batch rows (lane j = mode j of
// both). T2 fully pre-duplicated in regs ({tr,tr},{ti,ti} per k; 128
// regs) and shared by both rows. Per k: 2 LDS.64 broadcasts + 4 fma2,
// zero movs; 8 independent accumulator chains per warp.
// =====================================================================
static __device__ __forceinline__ void f_eval2(
    float2 V0, float2 V1,
    const u64* __restrict__ crr, const u64* __restrict__ cii,
    float2* __restrict__ s0, float2* __restrict__ s1,
    int lane, float wj, float nl2,
    float2& K0, float2& K1)
{
    s0[lane] = V0;
    s1[lane] = V1;
    __syncwarp();
    const u64* __restrict__ q0 = (const u64*)s0;
    const u64* __restrict__ q1 = (const u64*)s1;
    u64 Ea0 = 0, Fa0 = 0, Eb0 = 0, Fb0 = 0;
    u64 Ea1 = 0, Fa1 = 0, Eb1 = 0, Fb1 = 0;
    #pragma unroll
    for (int k = 0; k < NM; k += 2) {
        u64 Wa0 = q0[k];
        u64 Wa1 = q1[k];
        u64 Wb0 = q0[k + 1];
        u64 Wb1 = q1[k + 1];
        Ea0 = fma2(Wa0, crr[k], Ea0);     Fa0 = fma2(Wa0, cii[k], Fa0);
        Ea1 = fma2(Wa1, crr[k], Ea1);     Fa1 = fma2(Wa1, cii[k], Fa1);
        Eb0 = fma2(Wb0, crr[k + 1], Eb0); Fb0 = fma2(Wb0, cii[k + 1], Fb0);
        Eb1 = fma2(Wb1, crr[k + 1], Eb1); Fb1 = fma2(Wb1, cii[k + 1], Fb1);
    }
    // pr = sum tr*vr - ti*vi ; pi = sum tr*vi + ti*vr
    float pr0 = (lo32(Ea0) + lo32(Eb0)) - (hi32(Fa0) + hi32(Fb0));
    float pi0 = (hi32(Ea0) + hi32(Eb0)) + (lo32(Fa0) + lo32(Fb0));
    float pr1 = (lo32(Ea1) + lo32(Eb1)) - (hi32(Fa1) + hi32(Fb1));
    float pi1 = (hi32(Ea1) + hi32(Eb1)) + (lo32(Fa1) + lo32(Fb1));
    float w0 = fmaf(nl2, fmaf(V0.x, V0.x, V0.y * V0.y), wj);
    float w1 = fmaf(nl2, fmaf(V1.x, V1.x, V1.y * V1.y), wj);
    K0 = make_float2(fmaf(-w0, V0.y, pr0), fmaf(w0, V0.x, pi0));
    K1 = make_float2(fmaf(-w1, V1.y, pr1), fmaf(w1, V1.x, pi1));
}

__global__ void __launch_bounds__(ITHREADS, 1)
integrate_kernel(const float* __restrict__ A0r, const float* __restrict__ A0i,
                 const float* __restrict__ omega, const float* __restrict__ nl,
                 float* __restrict__ out,
                 int a0r_cap, int a0i_cap, int om_cap, int nl_cap,
                 long long cap_f, int pair_mode)
{
    __shared__ float2 shV[WPB][2][2][NM];   // [warp][pingpong][rowslot][mode], 7 KB

    const int warp = threadIdx.x >> 5;
    const int lane = threadIdx.x & 31;
    const int r0 = blockIdx.x * RPB + warp;       // first row of this warp
    const int r1 = r0 + WPB;                      // second row
    const bool v0 = (r0 < NB);
    const bool v1 = (r1 < NB);

    // T2 row for this lane, fully duplicated: {tr,tr} and {ti,ti} per k.
    u64 crr[NM], cii[NM];
    #pragma unroll
    for (int k = 0; k < NM; k++) {
        float2 t = g_T2[lane * NM + k];
        crr[k] = packf2(t.x, t.x);
        cii[k] = packf2(t.y, t.y);
    }

    const float wj  = rg(omega, lane, om_cap);
    const float nv  = rg(nl, 0, nl_cap);
    const float nl2 = nv * nv;

    float2 A0 = make_float2(1.0f, 0.0f);
    float2 A1 = make_float2(1.0f, 0.0f);
    if (lane < NIN) {
        A0.x = rg(A0r, r0 * NIN + lane, a0r_cap);
        A0.y = rg(A0i, r0 * NIN + lane, a0i_cap);
        A1.x = rg(A0r, r1 * NIN + lane, a0r_cap);
        A1.y = rg(A0i, r1 * NIN + lane, a0i_cap);
    }
    // invalid rows: A* computed but never stored

    const long long stride_c = (long long)NB * NM;
    long long c0 = (long long)r0 * NM + lane;
    long long c1 = (long long)r1 * NM + lane;

    if (pair_mode) {
        long long o;
        o = 2 * c0; if (v0 && o + 1 < cap_f) { out[o] = A0.x; out[o + 1] = A0.y; }
        o = 2 * c1; if (v1 && o + 1 < cap_f) { out[o] = A1.x; out[o + 1] = A1.y; }
    } else {
        if (v0 && c0 < cap_f) out[c0] = A0.x;
        if (v1 && c1 < cap_f) out[c1] = A1.x;
    }

    const double dtd = 1.0 / (double)NSTEPS;
    const float dtf = (float)dtd;
    const float hdt = (float)(0.5 * dtd);
    const float dt6 = (float)(dtd / 6.0);

    float2* s00 = &shV[warp][0][0][0];
    float2* s01 = &shV[warp][0][1][0];
    float2* s10 = &shV[warp][1][0][0];
    float2* s11 = &shV[warp][1][1][0];

    for (int step = 0; step < NSTEPS; step++) {
        float2 k1a, k1b, k2a, k2b, k3a, k3b, k4a, k4b;
        f_eval2(A0, A1, crr, cii, s00, s01, lane, wj, nl2, k1a, k1b);
        float2 sta = make_float2(fmaf(hdt, k1a.x, A0.x), fmaf(hdt, k1a.y, A0.y));
        float2 stb = make_float2(fmaf(hdt, k1b.x, A1.x), fmaf(hdt, k1b.y, A1.y));
        f_eval2(sta, stb, crr, cii, s10, s11, lane, wj, nl2, k2a, k2b);
        sta = make_float2(fmaf(hdt, k2a.x, A0.x), fmaf(hdt, k2a.y, A0.y));
        stb = make_float2(fmaf(hdt, k2b.x, A1.x), fmaf(hdt, k2b.y, A1.y));
        f_eval2(sta, stb, crr, cii, s00, s01, lane, wj, nl2, k3a, k3b);
        sta = make_float2(fmaf(dtf, k3a.x, A0.x), fmaf(dtf, k3a.y, A0.y));
        stb = make_float2(fmaf(dtf, k3b.x, A1.x), fmaf(dtf, k3b.y, A1.y));
        f_eval2(sta, stb, crr, cii, s10, s11, lane, wj, nl2, k4a, k4b);

        float sx0 = k1a.x + 2.0f * (k2a.x + k3a.x) + k4a.x;
        float sy0 = k1a.y + 2.0f * (k2a.y + k3a.y) + k4a.y;
        float sx1 = k1b.x + 2.0f * (k2b.x + k3b.x) + k4b.x;
        float sy1 = k1b.y + 2.0f * (k2b.y + k3b.y) + k4b.y;
        A0.x = fmaf(dt6, sx0, A0.x);
        A0.y = fmaf(dt6, sy0, A0.y);
        A1.x = fmaf(dt6, sx1, A1.x);
        A1.y = fmaf(dt6, sy1, A1.y);

        c0 += stride_c;
        c1 += stride_c;
        if (pair_mode) {
            long long o;
            o = 2 * c0; if (v0 && o + 1 < cap_f) { out[o] = A0.x; out[o + 1] = A0.y; }
            o = 2 * c1; if (v1 && o + 1 < cap_f) { out[o] = A1.x; out[o + 1] = A1.y; }
        } else {
            if (v0 && c0 < cap_f) out[c0] = A0.x;
            if (v1 && c1 < cap_f) out[c1] = A1.x;
        }
    }
}

extern "C" void kernel_launch(void* const* d_in, const int* in_sizes, int n_in,
                              void* d_out, int out_size)
{
    // Positional binding per documented metadata order:
    //   A0_real, A0_imag, omega, kappa, nonlinearity, params
    const long long want[6] = {NB * NIN, NB * NIN, NM, NM, 1, NM * NM - 1};
    const float* P[6];
    int cap[6];
    for (int j = 0; j < 6; j++) {
        if (j < n_in) {
            P[j] = (const float*)d_in[j];
            long long s = in_sizes[j];
            cap[j] = (int)(s < want[j] ? s : want[j]);
        } else {
            P[j] = (const float*)d_out;   // never dereferenced (cap 0)
            cap[j] = 0;
        }
    }

    // Output interpretation — identical to the passing round 10/12/13 logic.
    const long long PAIRS_F = 26214400LL;   // 2 * 200*2048*32
    long long cap_f = (long long)out_size;
    int pair_mode = (cap_f >= PAIRS_F) ? 1 : 0;
    if (cap_f > PAIRS_F) cap_f = PAIRS_F;

    prelude_kernel<<<1, PTHREADS>>>(P[3], P[5], cap[3], cap[5]);
    integrate_kernel<<<IGRID, ITHREADS>>>(P[0], P[1], P[2], P[4],
                                          (float*)d_out,
                                          cap[0], cap[1], cap[2], cap[4],
                                          cap_f, pair_mode);
}